// round 1
// baseline (speedup 1.0000x reference)
#include <cuda_runtime.h>
#include <cuda_bf16.h>

// Problem shape (fixed by the dataset): words (32, 4096, 768) f32,
// diff (32, 4096) f32 [UNUSED by reference], W (1, 1536) f32, b (1,) f32.
// out: (32, 1) f32.
#define B 32
#define L 4096
#define H 768
#define TWOH 1536
#define NROWS (B * L)
#define NEGV (-1e30f)

// Scratch for s/t projections: 2 * 32 * 4096 floats = 1 MB.
__device__ float g_s[NROWS];
__device__ float g_t[NROWS];

// ---------------------------------------------------------------------------
// Kernel 1: s[row] = words[row]·w1, t[row] = words[row]·w2.
// Warp-per-row, float4 vectorized. Each lane handles 6 float4 (24 floats)
// of the 768-wide row -> lanes read 512B contiguous per unrolled step.
// ---------------------------------------------------------------------------
__global__ __launch_bounds__(256) void ww_proj_kernel(
    const float* __restrict__ words,
    const float* __restrict__ W)
{
    __shared__ float sw[TWOH];  // w1 | w2
    for (int i = threadIdx.x; i < TWOH; i += blockDim.x) sw[i] = W[i];
    __syncthreads();

    const float4* w1v = reinterpret_cast<const float4*>(sw);
    const float4* w2v = reinterpret_cast<const float4*>(sw + H);

    const int lane    = threadIdx.x & 31;
    const int gwarp   = (blockIdx.x * blockDim.x + threadIdx.x) >> 5;
    const int nwarps  = (gridDim.x * blockDim.x) >> 5;

    for (int row = gwarp; row < NROWS; row += nwarps) {
        const float4* wp = reinterpret_cast<const float4*>(
            words + (size_t)row * H);
        float s = 0.f, t = 0.f;
#pragma unroll
        for (int i = 0; i < H / 128; i++) {           // 6 steps
            const int idx = lane + i * 32;
            const float4 v  = wp[idx];
            const float4 a  = w1v[idx];
            const float4 b2 = w2v[idx];
            s = fmaf(v.x, a.x,  fmaf(v.y, a.y,  fmaf(v.z, a.z,  fmaf(v.w, a.w,  s))));
            t = fmaf(v.x, b2.x, fmaf(v.y, b2.y, fmaf(v.z, b2.z, fmaf(v.w, b2.w, t))));
        }
#pragma unroll
        for (int off = 16; off > 0; off >>= 1) {
            s += __shfl_xor_sync(0xFFFFFFFFu, s, off);
            t += __shfl_xor_sync(0xFFFFFFFFu, t, off);
        }
        if (lane == 0) {
            g_s[row] = s;
            g_t[row] = t;
        }
    }
}

// ---------------------------------------------------------------------------
// Kernel 2: per batch, out[b] = max(0, max_{l, k in 1..5, l+k<L}(s[l]+t[l+k]) + bias).
// relu/max commute; NEG padding through relu yields 0, so clamp at 0 suffices.
// One block per batch; t staged in shared with NEG tail padding.
// ---------------------------------------------------------------------------
__global__ __launch_bounds__(256) void ww_reduce_kernel(
    const float* __restrict__ bias,
    float* __restrict__ out)
{
    const int b = blockIdx.x;
    const float* __restrict__ s = g_s + (size_t)b * L;
    const float* __restrict__ t = g_t + (size_t)b * L;

    __shared__ float st[L + 8];
    for (int i = threadIdx.x; i < L; i += blockDim.x) st[i] = t[i];
    if (threadIdx.x < 8) st[L + threadIdx.x] = NEGV;
    __syncthreads();

    float m = NEGV;
    for (int l = threadIdx.x; l < L; l += blockDim.x) {
        float tm = st[l + 1];
        tm = fmaxf(tm, st[l + 2]);
        tm = fmaxf(tm, st[l + 3]);
        tm = fmaxf(tm, st[l + 4]);
        tm = fmaxf(tm, st[l + 5]);
        m = fmaxf(m, s[l] + tm);
    }

    // block max-reduce
#pragma unroll
    for (int off = 16; off > 0; off >>= 1)
        m = fmaxf(m, __shfl_xor_sync(0xFFFFFFFFu, m, off));

    __shared__ float red[8];
    const int wid = threadIdx.x >> 5;
    if ((threadIdx.x & 31) == 0) red[wid] = m;
    __syncthreads();
    if (threadIdx.x == 0) {
        float mm = red[0];
#pragma unroll
        for (int w = 1; w < 8; w++) mm = fmaxf(mm, red[w]);
        out[b] = fmaxf(0.0f, mm + bias[0]);
    }
}

extern "C" void kernel_launch(void* const* d_in, const int* in_sizes, int n_in,
                              void* d_out, int out_size)
{
    const float* words = (const float*)d_in[0];
    // d_in[1] = diff : unused by the reference computation
    const float* W     = (const float*)d_in[2];
    const float* bias  = (const float*)d_in[3];
    float* out         = (float*)d_out;

    // 2048 blocks x 256 threads = 16384 warps; 131072 rows -> 8 rows/warp.
    ww_proj_kernel<<<2048, 256>>>(words, W);
    ww_reduce_kernel<<<B, 256>>>(bias, out);
}

// round 2
// speedup vs baseline: 1.1461x; 1.1461x over previous
#include <cuda_runtime.h>
#include <cuda_bf16.h>

// Shape (fixed): words (32, 4096, 768) f32, diff (32,4096) [unused],
// W (1,1536) f32, b (1,) f32 -> out (32,1) f32.
#define B 32
#define L 4096
#define H 768
#define TWOH 1536
#define NEGV (-1e30f)

// Chunking: each block owns R rows of one batch.
#define CHUNKS 64
#define R (L / CHUNKS)          // 64
#define NCHUNK (B * CHUNKS)     // 2048

// Per-chunk exports: internal max, last-5 s, first-5 t. (~90 KB)
__device__ float g_cmax[NCHUNK];
__device__ float g_stail[NCHUNK * 5];
__device__ float g_thead[NCHUNK * 5];

// ---------------------------------------------------------------------------
// Fused kernel: per 64-row chunk -> s,t projections (warp-per-row, float4,
// streaming loads) + internal windowed max + boundary exports.
// ---------------------------------------------------------------------------
__global__ __launch_bounds__(256) void ww_fused_kernel(
    const float* __restrict__ words,
    const float* __restrict__ W)
{
    __shared__ float sw[TWOH];       // w1 | w2
    __shared__ float s_sh[R];
    __shared__ float t_sh[R];
    __shared__ float red[8];

    for (int i = threadIdx.x; i < TWOH; i += blockDim.x) sw[i] = W[i];
    __syncthreads();

    const float4* w1v = reinterpret_cast<const float4*>(sw);
    const float4* w2v = reinterpret_cast<const float4*>(sw + H);

    const int c    = blockIdx.x;          // chunk id, 0..2047
    const int b    = c / CHUNKS;
    const int ch   = c % CHUNKS;
    const int row0 = b * L + ch * R;

    const int warp = threadIdx.x >> 5;
    const int lane = threadIdx.x & 31;

    // 8 warps x 8 rows each
    for (int r = warp; r < R; r += 8) {
        const float4* wp = reinterpret_cast<const float4*>(
            words + (size_t)(row0 + r) * H);
        float s = 0.f, t = 0.f;
#pragma unroll
        for (int i = 0; i < H / 128; i++) {        // 6 steps, 512B/warp/step
            const int idx = lane + i * 32;
            const float4 v  = __ldcs(wp + idx);    // read-once streaming
            const float4 a  = w1v[idx];
            const float4 b2 = w2v[idx];
            s = fmaf(v.x, a.x,  fmaf(v.y, a.y,  fmaf(v.z, a.z,  fmaf(v.w, a.w,  s))));
            t = fmaf(v.x, b2.x, fmaf(v.y, b2.y, fmaf(v.z, b2.z, fmaf(v.w, b2.w, t))));
        }
#pragma unroll
        for (int off = 16; off > 0; off >>= 1) {
            s += __shfl_xor_sync(0xFFFFFFFFu, s, off);
            t += __shfl_xor_sync(0xFFFFFFFFu, t, off);
        }
        if (lane == 0) {
            s_sh[r] = s;
            t_sh[r] = t;
        }
    }
    __syncthreads();

    // Internal windowed max: pairs (l, l+k), k=1..5, fully inside this chunk.
    float m = NEGV;
    if (threadIdx.x < R) {
        const int l = threadIdx.x;
        const float sl = s_sh[l];
#pragma unroll
        for (int k = 1; k <= 5; k++)
            if (l + k < R) m = fmaxf(m, sl + t_sh[l + k]);
    }
#pragma unroll
    for (int off = 16; off > 0; off >>= 1)
        m = fmaxf(m, __shfl_xor_sync(0xFFFFFFFFu, m, off));
    if (lane == 0) red[warp] = m;
    __syncthreads();
    if (threadIdx.x == 0) {
        float mm = red[0];
#pragma unroll
        for (int w = 1; w < 8; w++) mm = fmaxf(mm, red[w]);
        g_cmax[c] = mm;
    }
    if (threadIdx.x < 5) {
        g_thead[c * 5 + threadIdx.x] = t_sh[threadIdx.x];
        g_stail[c * 5 + threadIdx.x] = s_sh[R - 5 + threadIdx.x];
    }
}

// ---------------------------------------------------------------------------
// Finisher: per batch, combine 64 chunk maxes + 63 boundaries (15 pairs each),
// apply bias + relu. Boundary pairs: l = R-5+i (tail i), l+k = R+j (head j),
// k = 5-i+j in [1,5]  <=>  j <= i.
// ---------------------------------------------------------------------------
__global__ __launch_bounds__(64) void ww_final_kernel(
    const float* __restrict__ bias,
    float* __restrict__ out)
{
    __shared__ float red[2];
    const int b  = blockIdx.x;
    const int t  = threadIdx.x;
    const int c0 = b * CHUNKS;

    float m = NEGV;
    if (t < CHUNKS) m = g_cmax[c0 + t];
    if (t < CHUNKS - 1) {
        const int c = c0 + t;
#pragma unroll
        for (int i = 0; i < 5; i++) {
            const float st = g_stail[c * 5 + i];
#pragma unroll
            for (int j = 0; j < 5; j++)
                if (j <= i)
                    m = fmaxf(m, st + g_thead[(c + 1) * 5 + j]);
        }
    }
#pragma unroll
    for (int off = 16; off > 0; off >>= 1)
        m = fmaxf(m, __shfl_xor_sync(0xFFFFFFFFu, m, off));
    if ((t & 31) == 0) red[t >> 5] = m;
    __syncthreads();
    if (t == 0)
        out[b] = fmaxf(0.0f, fmaxf(red[0], red[1]) + bias[0]);
}

extern "C" void kernel_launch(void* const* d_in, const int* in_sizes, int n_in,
                              void* d_out, int out_size)
{
    const float* words = (const float*)d_in[0];
    // d_in[1] = diff : unused by the reference computation
    const float* W     = (const float*)d_in[2];
    const float* bias  = (const float*)d_in[3];
    float* out         = (float*)d_out;

    ww_fused_kernel<<<NCHUNK, 256>>>(words, W);
    ww_final_kernel<<<B, 64>>>(bias, out);
}

// round 3
// speedup vs baseline: 1.1521x; 1.0052x over previous
#include <cuda_runtime.h>
#include <cuda_bf16.h>

// Shape (fixed): words (32, 4096, 768) f32, diff (32,4096) [unused],
// W (1,1536) f32, b (1,) f32 -> out (32,1) f32.
#define B 32
#define L 4096
#define H 768
#define TWOH 1536
#define NEGV (-1e30f)

// Chunking: each block owns R rows of one batch.
#define CHUNKS 32               // chunks per batch
#define R (L / CHUNKS)          // 128 rows per chunk
#define NCHUNK (B * CHUNKS)     // 1024 blocks

// Per-chunk exports + completion ticket.
__device__ float g_cmax[NCHUNK];
__device__ float g_stail[NCHUNK * 5];
__device__ float g_thead[NCHUNK * 5];
__device__ unsigned int g_ticket = 0;

// ---------------------------------------------------------------------------
// Single fused kernel:
//   phase 1 (all blocks): s/t projections (warp-per-row, float4 streaming),
//     internal windowed max (pairs fully inside the chunk), boundary exports.
//   phase 2 (last block only, via ticket): combine chunk maxes + boundary
//     pairs + bias/relu -> out[32].
// Boundary pairs between chunk c and c+1: l = R-5+i (tail i), l+k = R+j
// (head j), k = 5-i+j in [1,5]  <=>  j <= i.
// ---------------------------------------------------------------------------
__global__ __launch_bounds__(256) void ww_fused_kernel(
    const float* __restrict__ words,
    const float* __restrict__ W,
    const float* __restrict__ bias,
    float* __restrict__ out)
{
    __shared__ float sw[TWOH];       // w1 | w2
    __shared__ float s_sh[R];
    __shared__ float t_sh[R];
    __shared__ float red[8];
    __shared__ unsigned int s_last;

    for (int i = threadIdx.x; i < TWOH; i += blockDim.x) sw[i] = W[i];
    __syncthreads();

    const float4* w1v = reinterpret_cast<const float4*>(sw);
    const float4* w2v = reinterpret_cast<const float4*>(sw + H);

    const int c    = blockIdx.x;          // chunk id, 0..NCHUNK-1
    const int b    = c / CHUNKS;
    const int ch   = c % CHUNKS;
    const int row0 = b * L + ch * R;

    const int warp = threadIdx.x >> 5;
    const int lane = threadIdx.x & 31;

    // 8 warps x 16 rows each
    for (int r = warp; r < R; r += 8) {
        const float4* wp = reinterpret_cast<const float4*>(
            words + (size_t)(row0 + r) * H);
        float s = 0.f, t = 0.f;
#pragma unroll
        for (int i = 0; i < H / 128; i++) {        // 6 steps, 512B/warp/step
            const int idx = lane + i * 32;
            const float4 v  = __ldcs(wp + idx);    // read-once streaming
            const float4 a  = w1v[idx];
            const float4 b2 = w2v[idx];
            s = fmaf(v.x, a.x,  fmaf(v.y, a.y,  fmaf(v.z, a.z,  fmaf(v.w, a.w,  s))));
            t = fmaf(v.x, b2.x, fmaf(v.y, b2.y, fmaf(v.z, b2.z, fmaf(v.w, b2.w, t))));
        }
#pragma unroll
        for (int off = 16; off > 0; off >>= 1) {
            s += __shfl_xor_sync(0xFFFFFFFFu, s, off);
            t += __shfl_xor_sync(0xFFFFFFFFu, t, off);
        }
        if (lane == 0) {
            s_sh[r] = s;
            t_sh[r] = t;
        }
    }
    __syncthreads();

    // Internal windowed max: each thread handles rows l = tid and tid+128? No:
    // R=128 rows, 256 threads -> threads 0..127 each take one l.
    float m = NEGV;
    if (threadIdx.x < R) {
        const int l = threadIdx.x;
        const float sl = s_sh[l];
#pragma unroll
        for (int k = 1; k <= 5; k++)
            if (l + k < R) m = fmaxf(m, sl + t_sh[l + k]);
    }
#pragma unroll
    for (int off = 16; off > 0; off >>= 1)
        m = fmaxf(m, __shfl_xor_sync(0xFFFFFFFFu, m, off));
    if (lane == 0) red[warp] = m;
    __syncthreads();
    if (threadIdx.x == 0) {
        float mm = red[0];
#pragma unroll
        for (int w = 1; w < 8; w++) mm = fmaxf(mm, red[w]);
        g_cmax[c] = mm;
    }
    if (threadIdx.x < 5) {
        g_thead[c * 5 + threadIdx.x] = t_sh[threadIdx.x];
        g_stail[c * 5 + threadIdx.x] = s_sh[R - 5 + threadIdx.x];
    }
    __syncthreads();

    // --- ticket: last block to finish does the final reduction ---
    if (threadIdx.x == 0) {
        __threadfence();
        s_last = atomicAdd(&g_ticket, 1u);
    }
    __syncthreads();
    if (s_last != NCHUNK - 1) return;
    __threadfence();   // acquire: see all blocks' exports

    // Final reduction: 256 threads = 32 batches x 8 threads.
    // Each thread handles CHUNKS/8 = 4 chunks of its batch.
    {
        const int fb  = threadIdx.x >> 3;   // batch 0..31
        const int sub = threadIdx.x & 7;    // 0..7
        float fm = NEGV;
#pragma unroll
        for (int q = 0; q < CHUNKS / 8; q++) {
            const int lc = sub * (CHUNKS / 8) + q;      // local chunk 0..31
            const int cc = fb * CHUNKS + lc;
            fm = fmaxf(fm, g_cmax[cc]);
            if (lc < CHUNKS - 1) {
#pragma unroll
                for (int i = 0; i < 5; i++) {
                    const float st = g_stail[cc * 5 + i];
#pragma unroll
                    for (int j = 0; j < 5; j++)
                        if (j <= i)
                            fm = fmaxf(fm, st + g_thead[(cc + 1) * 5 + j]);
                }
            }
        }
        // reduce across the 8 threads of this batch (contiguous lanes)
#pragma unroll
        for (int off = 4; off > 0; off >>= 1)
            fm = fmaxf(fm, __shfl_xor_sync(0xFFFFFFFFu, fm, off));
        if (sub == 0)
            out[fb] = fmaxf(0.0f, fm + bias[0]);
    }
    __syncthreads();
    if (threadIdx.x == 0) g_ticket = 0;     // reset for next graph replay
}

extern "C" void kernel_launch(void* const* d_in, const int* in_sizes, int n_in,
                              void* d_out, int out_size)
{
    const float* words = (const float*)d_in[0];
    // d_in[1] = diff : unused by the reference computation
    const float* W     = (const float*)d_in[2];
    const float* bias  = (const float*)d_in[3];
    float* out         = (float*)d_out;

    ww_fused_kernel<<<NCHUNK, 256>>>(words, W, bias, out);
}